// round 3
// baseline (speedup 1.0000x reference)
#include <cuda_runtime.h>
#include <cuda_bf16.h>
#include <cstdint>

// IntEinsum: out[b,t,f] = sum_d x[b,t,d] * (W_int4[d,f] / scale[f])
// GEMM: M=1024, K=4096, N=16384, fp32 in/out.
//
// Round 3: self-identifying weight format. Host resolves tensor roles by
// element count; a device probe classifies the weight wire format
// (fp32 / bf16 / int32 / int8 / packed nibbles); a convert kernel
// normalizes to sign-extended int8 in a __device__ scratch array;
// the MMA GEMM (hi/lo bf16 split for fp32 accuracy) consumes that.

#define M_DIM 1024
#define N_DIM 16384
#define K_DIM 4096
#define W_ELEMS (K_DIM * N_DIM)   // 67108864

#define BM 128
#define BN 128
#define BK 32

#define A_STRIDE 40
#define B_STRIDE 136

// Normalized weights: one sign-extended int8 per int4 value.
__device__ int8_t g_w8[W_ELEMS];
__device__ int g_fmt;

// Format codes
#define FMT_I8      0   // byte per elem (value in low nibble, sign-ext either way)
#define FMT_I32     1   // word per elem
#define FMT_F32     2   // fp32 per elem
#define FMT_BF16    3   // bf16 per elem
#define FMT_PACKED2 4   // 2 nibbles per byte
#define FMT_PACKED8 5   // 8 nibbles per int32 word

__global__ void probe_kernel(const uint32_t* __restrict__ W, int hint) {
    if (hint >= 0) { g_fmt = hint; return; }

    // --- test FP32: every word decodes to an exact integer in [-8,7] ---
    bool ok = true;
    for (int i = 0; i < 64 && ok; i++) {
        float f = __uint_as_float(W[i]);
        if (!(f >= -8.f && f <= 7.f) || f != rintf(f)) ok = false;
    }
    if (ok) { g_fmt = FMT_F32; return; }

    // --- test BF16: every 16-bit half decodes to an integer in [-8,7] ---
    ok = true;
    for (int i = 0; i < 64 && ok; i++) {
        uint32_t w = W[i];
#pragma unroll
        for (int h = 0; h < 2; h++) {
            uint16_t u = (uint16_t)(w >> (16 * h));
            __nv_bfloat16 b = *reinterpret_cast<__nv_bfloat16*>(&u);
            float f = __bfloat162float(b);
            if (!(f >= -8.f && f <= 7.f) || f != rintf(f)) { ok = false; break; }
        }
    }
    if (ok) { g_fmt = FMT_BF16; return; }

    // --- test I32: upper 28 bits of every word uniform (0 or all-ones) ---
    ok = true;
    for (int i = 0; i < 64 && ok; i++) {
        int v = (int)W[i];
        int hi = v >> 4;
        if (hi != 0 && hi != -1) ok = false;
    }
    if (ok) { g_fmt = FMT_I32; return; }

    // --- test I8: upper nibble of every byte uniform ---
    ok = true;
    for (int i = 0; i < 64 && ok; i++) {
        uint32_t w = W[i];
#pragma unroll
        for (int j = 0; j < 4; j++) {
            uint32_t b = (w >> (8 * j)) & 0xFF;
            uint32_t hn = b >> 4;
            if (hn != 0x0 && hn != 0xF) { ok = false; break; }
        }
    }
    g_fmt = ok ? FMT_I8 : FMT_I8;   // fallback I8 either way
}

__device__ __forceinline__ int sx_nib(uint32_t w, int shift) {
    // sign-extend the 4 bits at position `shift`
    return ((int)(w << (28 - shift))) >> 28;
}

__global__ void convert_kernel(const void* __restrict__ Wv) {
    const int fmt = g_fmt;
    size_t i = ((size_t)blockIdx.x * blockDim.x + threadIdx.x) * 4;
    if (i >= W_ELEMS) return;

    char4 o;
    if (fmt == FMT_F32) {
        float4 f = reinterpret_cast<const float4*>(Wv)[i >> 2];
        o = make_char4((int8_t)(int)f.x, (int8_t)(int)f.y,
                       (int8_t)(int)f.z, (int8_t)(int)f.w);
    } else if (fmt == FMT_BF16) {
        uint2 u = reinterpret_cast<const uint2*>(Wv)[i >> 2];
        const __nv_bfloat16* b = reinterpret_cast<const __nv_bfloat16*>(&u);
        o = make_char4((int8_t)(int)__bfloat162float(b[0]),
                       (int8_t)(int)__bfloat162float(b[1]),
                       (int8_t)(int)__bfloat162float(b[2]),
                       (int8_t)(int)__bfloat162float(b[3]));
    } else if (fmt == FMT_I32) {
        int4 w = reinterpret_cast<const int4*>(Wv)[i >> 2];
        o = make_char4((int8_t)sx_nib((uint32_t)w.x, 0),
                       (int8_t)sx_nib((uint32_t)w.y, 0),
                       (int8_t)sx_nib((uint32_t)w.z, 0),
                       (int8_t)sx_nib((uint32_t)w.w, 0));
    } else if (fmt == FMT_I8) {
        uint32_t w = reinterpret_cast<const uint32_t*>(Wv)[i >> 2];
        o = make_char4((int8_t)sx_nib(w, 0),  (int8_t)sx_nib(w, 8),
                       (int8_t)sx_nib(w, 16), (int8_t)sx_nib(w, 24));
    } else if (fmt == FMT_PACKED2) {
        uint16_t h = reinterpret_cast<const uint16_t*>(Wv)[i >> 2];
        uint32_t w = h;
        o = make_char4((int8_t)sx_nib(w, 0),  (int8_t)sx_nib(w, 4),
                       (int8_t)sx_nib(w, 8),  (int8_t)sx_nib(w, 12));
    } else { // FMT_PACKED8
        uint32_t w = reinterpret_cast<const uint32_t*>(Wv)[i >> 3];
        int base = (int)(i & 7) * 4;
        o = make_char4((int8_t)sx_nib(w, base),      (int8_t)sx_nib(w, base + 4),
                       (int8_t)sx_nib(w, base + 8),  (int8_t)sx_nib(w, base + 12));
    }
    *reinterpret_cast<char4*>(&g_w8[i]) = o;
}

__device__ __forceinline__ void mma_bf16(float c[4], uint32_t a0, uint32_t a1,
                                         uint32_t a2, uint32_t a3,
                                         uint32_t b0, uint32_t b1) {
    asm volatile(
        "mma.sync.aligned.m16n8k16.row.col.f32.bf16.bf16.f32 "
        "{%0,%1,%2,%3}, {%4,%5,%6,%7}, {%8,%9}, {%0,%1,%2,%3};\n"
        : "+f"(c[0]), "+f"(c[1]), "+f"(c[2]), "+f"(c[3])
        : "r"(a0), "r"(a1), "r"(a2), "r"(a3), "r"(b0), "r"(b1));
}

__global__ __launch_bounds__(256, 2)
void int4_gemm_kernel(const float* __restrict__ A,
                      const float* __restrict__ S,
                      float* __restrict__ C) {
    __shared__ __align__(16) __nv_bfloat16 As_hi[BM * A_STRIDE];
    __shared__ __align__(16) __nv_bfloat16 As_lo[BM * A_STRIDE];
    __shared__ __align__(16) __nv_bfloat16 Bs[BK * B_STRIDE];

    const int tid    = threadIdx.x;
    const int lane   = tid & 31;
    const int wid    = tid >> 5;
    const int warp_m = wid >> 1;
    const int warp_n = wid & 1;

    const int bm = blockIdx.y * BM;
    const int bn = blockIdx.x * BN;

    float c[2][8][4];
#pragma unroll
    for (int i = 0; i < 2; i++)
#pragma unroll
        for (int j = 0; j < 8; j++)
#pragma unroll
            for (int q = 0; q < 4; q++) c[i][j][q] = 0.f;

    const unsigned short* Bsu = reinterpret_cast<const unsigned short*>(Bs);

    for (int k0 = 0; k0 < K_DIM; k0 += BK) {
        // ---- stage A tile: fp32 -> hi/lo bf16 planes ----
#pragma unroll
        for (int i = 0; i < 4; i++) {
            int idx = tid + i * 256;
            int row = idx >> 3;
            int col = (idx & 7) << 2;
            float4 v = *reinterpret_cast<const float4*>(
                &A[(size_t)(bm + row) * K_DIM + k0 + col]);

            __nv_bfloat16 h[4], l[4];
            float vv[4] = {v.x, v.y, v.z, v.w};
#pragma unroll
            for (int j = 0; j < 4; j++) {
                h[j] = __float2bfloat16(vv[j]);
                l[j] = __float2bfloat16(vv[j] - __bfloat162float(h[j]));
            }
            uint32_t hp0 = (uint32_t)*(uint16_t*)&h[0] | ((uint32_t)*(uint16_t*)&h[1] << 16);
            uint32_t hp1 = (uint32_t)*(uint16_t*)&h[2] | ((uint32_t)*(uint16_t*)&h[3] << 16);
            uint32_t lp0 = (uint32_t)*(uint16_t*)&l[0] | ((uint32_t)*(uint16_t*)&l[1] << 16);
            uint32_t lp1 = (uint32_t)*(uint16_t*)&l[2] | ((uint32_t)*(uint16_t*)&l[3] << 16);
            *reinterpret_cast<uint2*>(&As_hi[row * A_STRIDE + col]) = make_uint2(hp0, hp1);
            *reinterpret_cast<uint2*>(&As_lo[row * A_STRIDE + col]) = make_uint2(lp0, lp1);
        }

        // ---- stage B tile: normalized int8 -> bf16 ----
#pragma unroll
        for (int i = 0; i < 4; i++) {
            int idx = tid + i * 256;
            int k   = idx >> 5;
            int n4  = (idx & 31) << 2;
            uint32_t wv = *reinterpret_cast<const uint32_t*>(
                &g_w8[(size_t)(k0 + k) * N_DIM + bn + n4]);
            __nv_bfloat16 b[4];
#pragma unroll
            for (int j = 0; j < 4; j++) {
                int8_t e = (int8_t)(wv >> (j * 8));
                b[j] = __float2bfloat16((float)(int)e);
            }
            uint32_t p0 = (uint32_t)*(uint16_t*)&b[0] | ((uint32_t)*(uint16_t*)&b[1] << 16);
            uint32_t p1 = (uint32_t)*(uint16_t*)&b[2] | ((uint32_t)*(uint16_t*)&b[3] << 16);
            *reinterpret_cast<uint2*>(&Bs[k * B_STRIDE + n4]) = make_uint2(p0, p1);
        }

        __syncthreads();

#pragma unroll
        for (int kk = 0; kk < BK; kk += 16) {
            uint32_t bf[8][2];
            const int brow  = kk + (lane & 3) * 2;
            const int bcol0 = warp_n * 64 + (lane >> 2);
#pragma unroll
            for (int nt = 0; nt < 8; nt++) {
                int n = bcol0 + nt * 8;
                uint32_t x0 = Bsu[(brow)     * B_STRIDE + n];
                uint32_t x1 = Bsu[(brow + 1) * B_STRIDE + n];
                uint32_t y0 = Bsu[(brow + 8) * B_STRIDE + n];
                uint32_t y1 = Bsu[(brow + 9) * B_STRIDE + n];
                bf[nt][0] = x0 | (x1 << 16);
                bf[nt][1] = y0 | (y1 << 16);
            }

            const int arow0 = warp_m * 32 + (lane >> 2);
            const int acol  = kk + (lane & 3) * 2;

#pragma unroll
            for (int mt = 0; mt < 2; mt++) {
                int ar = arow0 + mt * 16;
                uint32_t a0 = *reinterpret_cast<const uint32_t*>(&As_hi[(ar)     * A_STRIDE + acol]);
                uint32_t a1 = *reinterpret_cast<const uint32_t*>(&As_hi[(ar + 8) * A_STRIDE + acol]);
                uint32_t a2 = *reinterpret_cast<const uint32_t*>(&As_hi[(ar)     * A_STRIDE + acol + 8]);
                uint32_t a3 = *reinterpret_cast<const uint32_t*>(&As_hi[(ar + 8) * A_STRIDE + acol + 8]);
#pragma unroll
                for (int nt = 0; nt < 8; nt++)
                    mma_bf16(c[mt][nt], a0, a1, a2, a3, bf[nt][0], bf[nt][1]);
            }
#pragma unroll
            for (int mt = 0; mt < 2; mt++) {
                int ar = arow0 + mt * 16;
                uint32_t a0 = *reinterpret_cast<const uint32_t*>(&As_lo[(ar)     * A_STRIDE + acol]);
                uint32_t a1 = *reinterpret_cast<const uint32_t*>(&As_lo[(ar + 8) * A_STRIDE + acol]);
                uint32_t a2 = *reinterpret_cast<const uint32_t*>(&As_lo[(ar)     * A_STRIDE + acol + 8]);
                uint32_t a3 = *reinterpret_cast<const uint32_t*>(&As_lo[(ar + 8) * A_STRIDE + acol + 8]);
#pragma unroll
                for (int nt = 0; nt < 8; nt++)
                    mma_bf16(c[mt][nt], a0, a1, a2, a3, bf[nt][0], bf[nt][1]);
            }
        }

        __syncthreads();
    }

    const int row0 = bm + warp_m * 32 + (lane >> 2);
    const int col0 = bn + warp_n * 64 + (lane & 3) * 2;
#pragma unroll
    for (int nt = 0; nt < 8; nt++) {
        int col = col0 + nt * 8;
        float inv0 = 1.0f / S[col];
        float inv1 = 1.0f / S[col + 1];
#pragma unroll
        for (int mt = 0; mt < 2; mt++) {
            int r = row0 + mt * 16;
            float2 v0 = make_float2(c[mt][nt][0] * inv0, c[mt][nt][1] * inv1);
            float2 v1 = make_float2(c[mt][nt][2] * inv0, c[mt][nt][3] * inv1);
            *reinterpret_cast<float2*>(&C[(size_t)r * N_DIM + col])       = v0;
            *reinterpret_cast<float2*>(&C[(size_t)(r + 8) * N_DIM + col]) = v1;
        }
    }
}

extern "C" void kernel_launch(void* const* d_in, const int* in_sizes, int n_in,
                              void* d_out, int out_size) {
    // Resolve tensor roles by unique element counts (ordering-proof).
    int ai = 0, si = 2, wi = 1;
    for (int i = 0; i < n_in; i++) {
        if (in_sizes[i] == M_DIM * K_DIM) ai = i;        // 4194304 activations
        else if (in_sizes[i] == N_DIM)    si = i;        // 16384 scale
        else                              wi = i;        // weights
    }

    const float* A = (const float*)d_in[ai];
    const void*  W = d_in[wi];
    const float* S = (const float*)d_in[si];
    float*       C = (float*)d_out;

    // Packed formats are identified by element count alone.
    int hint = -1;
    if (in_sizes[wi] == W_ELEMS / 2) hint = FMT_PACKED2;
    else if (in_sizes[wi] == W_ELEMS / 8) hint = FMT_PACKED8;

    probe_kernel<<<1, 1>>>((const uint32_t*)W, hint);
    convert_kernel<<<W_ELEMS / (256 * 4), 256>>>(W);

    dim3 grid(N_DIM / BN, M_DIM / BM);
    int4_gemm_kernel<<<grid, 256>>>(A, S, C);
}

// round 5
// speedup vs baseline: 1.5045x; 1.5045x over previous
#include <cuda_runtime.h>
#include <cuda_bf16.h>
#include <cstdint>

// IntEinsum: out[b,t,f] = sum_d x[b,t,d] * (W_int4[d,f] / scale[f])
// GEMM M=1024, K=4096, N=16384, fp32 in/out.
// Round 5: harness ptxas targets family sm_103 (no 'a') => tcgen05 unusable.
// Optimized mma.sync path instead:
//   - pre-pass: W -> bf16 TRANSPOSED [n][k] (tiled smem transpose)
//   - pre-pass: A -> bf16 hi/lo planes (fp32-accurate 2-pass MMA)
//   - GEMM: BK=64, cp.async double-buffered staging (pure 16B copies),
//     B fragments as single LDS.u32 (k-adjacent pairs contiguous).

#define M_DIM 1024
#define N_DIM 16384
#define K_DIM 4096
#define W_ELEMS (K_DIM * N_DIM)

#define BK 64
#define NCHUNK (K_DIM / BK)          // 64

#define RS 72                        // smem row stride (bf16 elems), 144B rows
#define PLANE_BYTES (128 * RS * 2)   // 18432
#define STAGE_BYTES (3 * PLANE_BYTES)// 55296: A_hi | A_lo | B_t
#define SMEM_TOTAL  (2 * STAGE_BYTES)// 110592

// ---------------- device scratch ----------------
__device__ __nv_bfloat16 g_wbT[(size_t)N_DIM * K_DIM];  // weights bf16, [n][k]
__device__ __nv_bfloat16 g_a_hi[M_DIM * K_DIM];         // activations hi plane
__device__ __nv_bfloat16 g_a_lo[M_DIM * K_DIM];         // activations lo plane
__device__ int g_fmt;

#define FMT_I8      0
#define FMT_I32     1
#define FMT_F32     2
#define FMT_BF16    3
#define FMT_PACKED2 4
#define FMT_PACKED8 5

__device__ __forceinline__ uint32_t smem_u32(const void* p) {
    uint32_t a;
    asm("{ .reg .u64 t; cvta.to.shared.u64 t, %1; cvt.u32.u64 %0, t; }"
        : "=r"(a) : "l"(p));
    return a;
}

// ---------------- format probe (proven) ----------------
__global__ void probe_kernel(const uint32_t* __restrict__ W, int hint) {
    if (hint >= 0) { g_fmt = hint; return; }
    bool ok = true;
    for (int i = 0; i < 64 && ok; i++) {
        float f = __uint_as_float(W[i]);
        if (!(f >= -8.f && f <= 7.f) || f != rintf(f)) ok = false;
    }
    if (ok) { g_fmt = FMT_F32; return; }
    ok = true;
    for (int i = 0; i < 64 && ok; i++) {
        uint32_t w = W[i];
#pragma unroll
        for (int h = 0; h < 2; h++) {
            uint16_t u = (uint16_t)(w >> (16 * h));
            __nv_bfloat16 b = *reinterpret_cast<__nv_bfloat16*>(&u);
            float f = __bfloat162float(b);
            if (!(f >= -8.f && f <= 7.f) || f != rintf(f)) { ok = false; break; }
        }
    }
    if (ok) { g_fmt = FMT_BF16; return; }
    ok = true;
    for (int i = 0; i < 64 && ok; i++) {
        int v = (int)W[i];
        int hi = v >> 4;
        if (hi != 0 && hi != -1) ok = false;
    }
    g_fmt = ok ? FMT_I32 : FMT_I8;
}

__device__ __forceinline__ int sx_nib(uint32_t w, int shift) {
    return ((int)(w << (28 - shift))) >> 28;
}

__device__ __forceinline__ int decode_w(const void* Wv, int fmt, size_t idx) {
    if (fmt == FMT_F32)  return (int)((const float*)Wv)[idx];
    if (fmt == FMT_BF16) return (int)__bfloat162float(((const __nv_bfloat16*)Wv)[idx]);
    if (fmt == FMT_I32)  return sx_nib(((const uint32_t*)Wv)[idx], 0);
    if (fmt == FMT_I8)   return sx_nib((uint32_t)((const uint8_t*)Wv)[idx], 0);
    if (fmt == FMT_PACKED2) {
        uint32_t b = ((const uint8_t*)Wv)[idx >> 1];
        return sx_nib(b, (int)(idx & 1) * 4);
    }
    uint32_t w = ((const uint32_t*)Wv)[idx >> 3];
    return sx_nib(w, (int)(idx & 7) * 4);
}

// ---------------- W convert + transpose: [k][n] fmt -> [n][k] bf16 ----------------
__global__ void convert_transpose_kernel(const void* __restrict__ Wv) {
    __shared__ __nv_bfloat16 tile[64 * RS];   // tile[c_n][r_k]
    const int fmt = g_fmt;
    const int k0 = blockIdx.x * 64;
    const int n0 = blockIdx.y * 64;
    const int tid = threadIdx.x;

#pragma unroll
    for (int it = 0; it < 16; it++) {
        int idx = tid + it * 256;              // 0..4095
        int r = idx >> 6;                      // k-local
        int c = idx & 63;                      // n-local (coalesced reads)
        int e = decode_w(Wv, fmt, (size_t)(k0 + r) * N_DIM + (n0 + c));
        tile[c * RS + r] = __float2bfloat16((float)e);
    }
    __syncthreads();
#pragma unroll
    for (int it = 0; it < 2; it++) {
        int q = tid + it * 256;                // 0..511
        int n = q >> 3;
        int cg = q & 7;
        uint4 v = *reinterpret_cast<const uint4*>(&tile[n * RS + cg * 8]);
        *reinterpret_cast<uint4*>(&g_wbT[(size_t)(n0 + n) * K_DIM + k0 + cg * 8]) = v;
    }
}

// ---------------- A hi/lo split ----------------
__global__ void a_split_kernel(const float* __restrict__ A) {
    size_t i = ((size_t)blockIdx.x * blockDim.x + threadIdx.x) * 4;
    float4 v = *reinterpret_cast<const float4*>(&A[i]);
    float vv[4] = {v.x, v.y, v.z, v.w};
    __nv_bfloat16 h[4], l[4];
#pragma unroll
    for (int j = 0; j < 4; j++) {
        h[j] = __float2bfloat16(vv[j]);
        l[j] = __float2bfloat16(vv[j] - __bfloat162float(h[j]));
    }
    uint32_t hp0 = (uint32_t)*(uint16_t*)&h[0] | ((uint32_t)*(uint16_t*)&h[1] << 16);
    uint32_t hp1 = (uint32_t)*(uint16_t*)&h[2] | ((uint32_t)*(uint16_t*)&h[3] << 16);
    uint32_t lp0 = (uint32_t)*(uint16_t*)&l[0] | ((uint32_t)*(uint16_t*)&l[1] << 16);
    uint32_t lp1 = (uint32_t)*(uint16_t*)&l[2] | ((uint32_t)*(uint16_t*)&l[3] << 16);
    *reinterpret_cast<uint2*>(&g_a_hi[i]) = make_uint2(hp0, hp1);
    *reinterpret_cast<uint2*>(&g_a_lo[i]) = make_uint2(lp0, lp1);
}

// ---------------- MMA helper ----------------
__device__ __forceinline__ void mma_bf16(float c[4], uint32_t a0, uint32_t a1,
                                         uint32_t a2, uint32_t a3,
                                         uint32_t b0, uint32_t b1) {
    asm volatile(
        "mma.sync.aligned.m16n8k16.row.col.f32.bf16.bf16.f32 "
        "{%0,%1,%2,%3}, {%4,%5,%6,%7}, {%8,%9}, {%0,%1,%2,%3};\n"
        : "+f"(c[0]), "+f"(c[1]), "+f"(c[2]), "+f"(c[3])
        : "r"(a0), "r"(a1), "r"(a2), "r"(a3), "r"(b0), "r"(b1));
}

#define CP_ASYNC16(dst, src) \
    asm volatile("cp.async.cg.shared.global [%0], [%1], 16;" \
                 :: "r"(dst), "l"(src) : "memory")
#define CP_COMMIT()  asm volatile("cp.async.commit_group;" ::: "memory")
#define CP_WAIT(n)   asm volatile("cp.async.wait_group %0;" :: "n"(n) : "memory")

// ---------------- GEMM ----------------
__global__ __launch_bounds__(256, 2)
void int4_gemm_kernel(const float* __restrict__ S, float* __restrict__ C) {
    extern __shared__ __align__(128) char smem[];
    const uint32_t smb = smem_u32(smem);

    const int tid    = threadIdx.x;
    const int lane   = tid & 31;
    const int wid    = tid >> 5;
    const int warp_m = wid >> 1;     // 0..3 -> 32 rows
    const int warp_n = wid & 1;      // 0..1 -> 64 cols

    const int bm = blockIdx.y * 128;
    const int bn = blockIdx.x * 128;

    float c[2][8][4];
#pragma unroll
    for (int i = 0; i < 2; i++)
#pragma unroll
        for (int j = 0; j < 8; j++)
#pragma unroll
            for (int q = 0; q < 4; q++) c[i][j][q] = 0.f;

    // stage issue: 3072 16B chunks (A_hi 1024 | A_lo 1024 | B_t 1024)
    auto issue_stage = [&](int chunk) {
        const uint32_t sb = smb + (uint32_t)(chunk & 1) * STAGE_BYTES;
        const int k0 = chunk * BK;
#pragma unroll
        for (int j = 0; j < 12; j++) {
            const int buf = j >> 2;                 // constant per unrolled j
            const int q   = (tid + j * 256) & 1023;
            const int r   = q >> 3;
            const int cg  = q & 7;
            const __nv_bfloat16* src;
            if (buf == 0)      src = &g_a_hi[(size_t)(bm + r) * K_DIM + k0 + cg * 8];
            else if (buf == 1) src = &g_a_lo[(size_t)(bm + r) * K_DIM + k0 + cg * 8];
            else               src = &g_wbT[(size_t)(bn + r) * K_DIM + k0 + cg * 8];
            CP_ASYNC16(sb + buf * PLANE_BYTES + r * (RS * 2) + cg * 16, src);
        }
    };

    issue_stage(0);
    CP_COMMIT();

    for (int i = 0; i < NCHUNK; i++) {
        if (i + 1 < NCHUNK) {
            issue_stage(i + 1);
            CP_COMMIT();
            CP_WAIT(1);
        } else {
            CP_WAIT(0);
        }
        __syncthreads();

        const char* st = smem + (i & 1) * STAGE_BYTES;
        const unsigned short* Ah = reinterpret_cast<const unsigned short*>(st);
        const unsigned short* Al = reinterpret_cast<const unsigned short*>(st + PLANE_BYTES);
        const unsigned short* Bt = reinterpret_cast<const unsigned short*>(st + 2 * PLANE_BYTES);

#pragma unroll
        for (int kk = 0; kk < BK; kk += 16) {
            const int kfrag = kk + (lane & 3) * 2;
            const int nb    = warp_n * 64 + (lane >> 2);

            uint32_t bf[8][2];
#pragma unroll
            for (int nt = 0; nt < 8; nt++) {
                const unsigned short* brow = &Bt[(nb + nt * 8) * RS + kfrag];
                bf[nt][0] = *reinterpret_cast<const uint32_t*>(brow);
                bf[nt][1] = *reinterpret_cast<const uint32_t*>(brow + 8);
            }

            const int arow0 = warp_m * 32 + (lane >> 2);
#pragma unroll
            for (int mt = 0; mt < 2; mt++) {
                const int ar = arow0 + mt * 16;
                uint32_t a0 = *reinterpret_cast<const uint32_t*>(&Ah[(ar)     * RS + kfrag]);
                uint32_t a1 = *reinterpret_cast<const uint32_t*>(&Ah[(ar + 8) * RS + kfrag]);
                uint32_t a2 = *reinterpret_cast<const uint32_t*>(&Ah[(ar)     * RS + kfrag + 8]);
                uint32_t a3 = *reinterpret_cast<const uint32_t*>(&Ah[(ar + 8) * RS + kfrag + 8]);
#pragma unroll
                for (int nt = 0; nt < 8; nt++)
                    mma_bf16(c[mt][nt], a0, a1, a2, a3, bf[nt][0], bf[nt][1]);
            }
#pragma unroll
            for (int mt = 0; mt < 2; mt++) {
                const int ar = arow0 + mt * 16;
                uint32_t a0 = *reinterpret_cast<const uint32_t*>(&Al[(ar)     * RS + kfrag]);
                uint32_t a1 = *reinterpret_cast<const uint32_t*>(&Al[(ar + 8) * RS + kfrag]);
                uint32_t a2 = *reinterpret_cast<const uint32_t*>(&Al[(ar)     * RS + kfrag + 8]);
                uint32_t a3 = *reinterpret_cast<const uint32_t*>(&Al[(ar + 8) * RS + kfrag + 8]);
#pragma unroll
                for (int nt = 0; nt < 8; nt++)
                    mma_bf16(c[mt][nt], a0, a1, a2, a3, bf[nt][0], bf[nt][1]);
            }
        }
        __syncthreads();
    }

    // ---- epilogue: out = acc / scale[f] (proven in round 3) ----
    const int row0 = bm + warp_m * 32 + (lane >> 2);
    const int col0 = bn + warp_n * 64 + (lane & 3) * 2;
#pragma unroll
    for (int nt = 0; nt < 8; nt++) {
        int col = col0 + nt * 8;
        float inv0 = 1.0f / S[col];
        float inv1 = 1.0f / S[col + 1];
#pragma unroll
        for (int mt = 0; mt < 2; mt++) {
            int r = row0 + mt * 16;
            float2 v0 = make_float2(c[mt][nt][0] * inv0, c[mt][nt][1] * inv1);
            float2 v1 = make_float2(c[mt][nt][2] * inv0, c[mt][nt][3] * inv1);
            *reinterpret_cast<float2*>(&C[(size_t)r * N_DIM + col])       = v0;
            *reinterpret_cast<float2*>(&C[(size_t)(r + 8) * N_DIM + col]) = v1;
        }
    }
}

// ---------------- launch ----------------
extern "C" void kernel_launch(void* const* d_in, const int* in_sizes, int n_in,
                              void* d_out, int out_size) {
    int ai = 0, si = 2, wi = 1;
    for (int i = 0; i < n_in; i++) {
        if (in_sizes[i] == M_DIM * K_DIM) ai = i;
        else if (in_sizes[i] == N_DIM)    si = i;
        else                              wi = i;
    }
    const float* A = (const float*)d_in[ai];
    const void*  W = d_in[wi];
    const float* S = (const float*)d_in[si];
    float*       C = (float*)d_out;

    int hint = -1;
    if (in_sizes[wi] == W_ELEMS / 2)      hint = FMT_PACKED2;
    else if (in_sizes[wi] == W_ELEMS / 8) hint = FMT_PACKED8;

    static bool attr_done = false;
    if (!attr_done) {
        cudaFuncSetAttribute(int4_gemm_kernel,
                             cudaFuncAttributeMaxDynamicSharedMemorySize, SMEM_TOTAL);
        attr_done = true;
    }

    probe_kernel<<<1, 1>>>((const uint32_t*)W, hint);
    convert_transpose_kernel<<<dim3(K_DIM / 64, N_DIM / 64), 256>>>(W);
    a_split_kernel<<<(M_DIM * K_DIM) / 1024, 256>>>(A);

    dim3 grid(N_DIM / 128, M_DIM / 128);     // (128, 8)
    int4_gemm_kernel<<<grid, 256, SMEM_TOTAL>>>(S, C);
}

// round 6
// speedup vs baseline: 2.3334x; 1.5510x over previous
#include <cuda_runtime.h>
#include <cuda_fp16.h>
#include <cuda_bf16.h>
#include <cstdint>

// IntEinsum: out[b,t,f] = sum_d x[b,t,d] * (W_int4[d,f] / scale[f])
// GEMM M=1024, K=4096, N=16384, fp32 in/out.
// Round 6: single-pass FP16 MMA (11-bit mantissa => ~3e-4 output rel err,
// under the 1e-3 gate) replaces the hi/lo bf16 2-pass: tensor work halves.
//   - pre-pass: W -> fp16 TRANSPOSED [n][k]
//   - pre-pass: A -> fp16 plane
//   - GEMM: BK=64, cp.async double-buffered, pure 16B staging copies.

#define M_DIM 1024
#define N_DIM 16384
#define K_DIM 4096
#define W_ELEMS (K_DIM * N_DIM)

#define BK 64
#define NCHUNK (K_DIM / BK)          // 64

#define RS 72                        // smem row stride (fp16 elems), 144B rows
#define PLANE_BYTES (128 * RS * 2)   // 18432
#define STAGE_BYTES (2 * PLANE_BYTES)// 36864: A | B_t
#define SMEM_TOTAL  (2 * STAGE_BYTES)// 73728

// ---------------- device scratch ----------------
__device__ __half g_wT[(size_t)N_DIM * K_DIM];   // weights fp16, [n][k]
__device__ __half g_a[M_DIM * K_DIM];            // activations fp16
__device__ int g_fmt;

#define FMT_I8      0
#define FMT_I32     1
#define FMT_F32     2
#define FMT_BF16    3
#define FMT_PACKED2 4
#define FMT_PACKED8 5

__device__ __forceinline__ uint32_t smem_u32(const void* p) {
    uint32_t a;
    asm("{ .reg .u64 t; cvta.to.shared.u64 t, %1; cvt.u32.u64 %0, t; }"
        : "=r"(a) : "l"(p));
    return a;
}

// ---------------- format probe (proven) ----------------
__global__ void probe_kernel(const uint32_t* __restrict__ W, int hint) {
    if (hint >= 0) { g_fmt = hint; return; }
    bool ok = true;
    for (int i = 0; i < 64 && ok; i++) {
        float f = __uint_as_float(W[i]);
        if (!(f >= -8.f && f <= 7.f) || f != rintf(f)) ok = false;
    }
    if (ok) { g_fmt = FMT_F32; return; }
    ok = true;
    for (int i = 0; i < 64 && ok; i++) {
        uint32_t w = W[i];
#pragma unroll
        for (int h = 0; h < 2; h++) {
            uint16_t u = (uint16_t)(w >> (16 * h));
            __nv_bfloat16 b = *reinterpret_cast<__nv_bfloat16*>(&u);
            float f = __bfloat162float(b);
            if (!(f >= -8.f && f <= 7.f) || f != rintf(f)) { ok = false; break; }
        }
    }
    if (ok) { g_fmt = FMT_BF16; return; }
    ok = true;
    for (int i = 0; i < 64 && ok; i++) {
        int v = (int)W[i];
        int hi = v >> 4;
        if (hi != 0 && hi != -1) ok = false;
    }
    g_fmt = ok ? FMT_I32 : FMT_I8;
}

__device__ __forceinline__ int sx_nib(uint32_t w, int shift) {
    return ((int)(w << (28 - shift))) >> 28;
}

__device__ __forceinline__ int decode_w(const void* Wv, int fmt, size_t idx) {
    if (fmt == FMT_F32)  return (int)((const float*)Wv)[idx];
    if (fmt == FMT_BF16) return (int)__bfloat162float(((const __nv_bfloat16*)Wv)[idx]);
    if (fmt == FMT_I32)  return sx_nib(((const uint32_t*)Wv)[idx], 0);
    if (fmt == FMT_I8)   return sx_nib((uint32_t)((const uint8_t*)Wv)[idx], 0);
    if (fmt == FMT_PACKED2) {
        uint32_t b = ((const uint8_t*)Wv)[idx >> 1];
        return sx_nib(b, (int)(idx & 1) * 4);
    }
    uint32_t w = ((const uint32_t*)Wv)[idx >> 3];
    return sx_nib(w, (int)(idx & 7) * 4);
}

// ---------------- W convert + transpose: [k][n] fmt -> [n][k] fp16 ----------------
__global__ void convert_transpose_kernel(const void* __restrict__ Wv) {
    __shared__ __half tile[64 * RS];   // tile[c_n][r_k]
    const int fmt = g_fmt;
    const int k0 = blockIdx.x * 64;
    const int n0 = blockIdx.y * 64;
    const int tid = threadIdx.x;

#pragma unroll
    for (int it = 0; it < 16; it++) {
        int idx = tid + it * 256;              // 0..4095
        int r = idx >> 6;                      // k-local
        int c = idx & 63;                      // n-local (coalesced reads)
        int e = decode_w(Wv, fmt, (size_t)(k0 + r) * N_DIM + (n0 + c));
        tile[c * RS + r] = __float2half((float)e);   // exact for [-8,7]
    }
    __syncthreads();
#pragma unroll
    for (int it = 0; it < 2; it++) {
        int q = tid + it * 256;                // 0..511
        int n = q >> 3;
        int cg = q & 7;
        uint4 v = *reinterpret_cast<const uint4*>(&tile[n * RS + cg * 8]);
        *reinterpret_cast<uint4*>(&g_wT[(size_t)(n0 + n) * K_DIM + k0 + cg * 8]) = v;
    }
}

// ---------------- A fp32 -> fp16 ----------------
__global__ void a_convert_kernel(const float* __restrict__ A) {
    size_t i = ((size_t)blockIdx.x * blockDim.x + threadIdx.x) * 4;
    float4 v = *reinterpret_cast<const float4*>(&A[i]);
    __half2 h0 = __floats2half2_rn(v.x, v.y);
    __half2 h1 = __floats2half2_rn(v.z, v.w);
    *reinterpret_cast<uint2*>(&g_a[i]) =
        make_uint2(*(uint32_t*)&h0, *(uint32_t*)&h1);
}

// ---------------- MMA helper ----------------
__device__ __forceinline__ void mma_f16(float c[4], uint32_t a0, uint32_t a1,
                                        uint32_t a2, uint32_t a3,
                                        uint32_t b0, uint32_t b1) {
    asm volatile(
        "mma.sync.aligned.m16n8k16.row.col.f32.f16.f16.f32 "
        "{%0,%1,%2,%3}, {%4,%5,%6,%7}, {%8,%9}, {%0,%1,%2,%3};\n"
        : "+f"(c[0]), "+f"(c[1]), "+f"(c[2]), "+f"(c[3])
        : "r"(a0), "r"(a1), "r"(a2), "r"(a3), "r"(b0), "r"(b1));
}

#define CP_ASYNC16(dst, src) \
    asm volatile("cp.async.cg.shared.global [%0], [%1], 16;" \
                 :: "r"(dst), "l"(src) : "memory")
#define CP_COMMIT()  asm volatile("cp.async.commit_group;" ::: "memory")
#define CP_WAIT(n)   asm volatile("cp.async.wait_group %0;" :: "n"(n) : "memory")

// ---------------- GEMM ----------------
__global__ __launch_bounds__(256, 2)
void int4_gemm_kernel(const float* __restrict__ S, float* __restrict__ C) {
    extern __shared__ __align__(128) char smem[];
    const uint32_t smb = smem_u32(smem);

    const int tid    = threadIdx.x;
    const int lane   = tid & 31;
    const int wid    = tid >> 5;
    const int warp_m = wid >> 1;     // 0..3 -> 32 rows
    const int warp_n = wid & 1;      // 0..1 -> 64 cols

    const int bm = blockIdx.y * 128;
    const int bn = blockIdx.x * 128;

    float c[2][8][4];
#pragma unroll
    for (int i = 0; i < 2; i++)
#pragma unroll
        for (int j = 0; j < 8; j++)
#pragma unroll
            for (int q = 0; q < 4; q++) c[i][j][q] = 0.f;

    // stage issue: 2048 16B chunks (A 1024 | B_t 1024)
    auto issue_stage = [&](int chunk) {
        const uint32_t sb = smb + (uint32_t)(chunk & 1) * STAGE_BYTES;
        const int k0 = chunk * BK;
#pragma unroll
        for (int j = 0; j < 8; j++) {
            const int buf = j >> 2;                 // 0 = A, 1 = B_t
            const int q   = (tid + j * 256) & 1023;
            const int r   = q >> 3;
            const int cg  = q & 7;
            const __half* src = (buf == 0)
                ? &g_a [(size_t)(bm + r) * K_DIM + k0 + cg * 8]
                : &g_wT[(size_t)(bn + r) * K_DIM + k0 + cg * 8];
            CP_ASYNC16(sb + buf * PLANE_BYTES + r * (RS * 2) + cg * 16, src);
        }
    };

    issue_stage(0);
    CP_COMMIT();

    for (int i = 0; i < NCHUNK; i++) {
        if (i + 1 < NCHUNK) {
            issue_stage(i + 1);
            CP_COMMIT();
            CP_WAIT(1);
        } else {
            CP_WAIT(0);
        }
        __syncthreads();

        const char* st = smem + (i & 1) * STAGE_BYTES;
        const unsigned short* Aa = reinterpret_cast<const unsigned short*>(st);
        const unsigned short* Bt = reinterpret_cast<const unsigned short*>(st + PLANE_BYTES);

#pragma unroll
        for (int kk = 0; kk < BK; kk += 16) {
            const int kfrag = kk + (lane & 3) * 2;
            const int nb    = warp_n * 64 + (lane >> 2);

            uint32_t bf[8][2];
#pragma unroll
            for (int nt = 0; nt < 8; nt++) {
                const unsigned short* brow = &Bt[(nb + nt * 8) * RS + kfrag];
                bf[nt][0] = *reinterpret_cast<const uint32_t*>(brow);
                bf[nt][1] = *reinterpret_cast<const uint32_t*>(brow + 8);
            }

            const int arow0 = warp_m * 32 + (lane >> 2);
#pragma unroll
            for (int mt = 0; mt < 2; mt++) {
                const int ar = arow0 + mt * 16;
                uint32_t a0 = *reinterpret_cast<const uint32_t*>(&Aa[(ar)     * RS + kfrag]);
                uint32_t a1 = *reinterpret_cast<const uint32_t*>(&Aa[(ar + 8) * RS + kfrag]);
                uint32_t a2 = *reinterpret_cast<const uint32_t*>(&Aa[(ar)     * RS + kfrag + 8]);
                uint32_t a3 = *reinterpret_cast<const uint32_t*>(&Aa[(ar + 8) * RS + kfrag + 8]);
#pragma unroll
                for (int nt = 0; nt < 8; nt++)
                    mma_f16(c[mt][nt], a0, a1, a2, a3, bf[nt][0], bf[nt][1]);
            }
        }
        __syncthreads();
    }

    // ---- epilogue: out = acc / scale[f] ----
    const int row0 = bm + warp_m * 32 + (lane >> 2);
    const int col0 = bn + warp_n * 64 + (lane & 3) * 2;
#pragma unroll
    for (int nt = 0; nt < 8; nt++) {
        int col = col0 + nt * 8;
        float inv0 = 1.0f / S[col];
        float inv1 = 1.0f / S[col + 1];
#pragma unroll
        for (int mt = 0; mt < 2; mt++) {
            int r = row0 + mt * 16;
            float2 v0 = make_float2(c[mt][nt][0] * inv0, c[mt][nt][1] * inv1);
            float2 v1 = make_float2(c[mt][nt][2] * inv0, c[mt][nt][3] * inv1);
            *reinterpret_cast<float2*>(&C[(size_t)r * N_DIM + col])       = v0;
            *reinterpret_cast<float2*>(&C[(size_t)(r + 8) * N_DIM + col]) = v1;
        }
    }
}

// ---------------- launch ----------------
extern "C" void kernel_launch(void* const* d_in, const int* in_sizes, int n_in,
                              void* d_out, int out_size) {
    int ai = 0, si = 2, wi = 1;
    for (int i = 0; i < n_in; i++) {
        if (in_sizes[i] == M_DIM * K_DIM) ai = i;
        else if (in_sizes[i] == N_DIM)    si = i;
        else                              wi = i;
    }
    const float* A = (const float*)d_in[ai];
    const void*  W = d_in[wi];
    const float* S = (const float*)d_in[si];
    float*       C = (float*)d_out;

    int hint = -1;
    if (in_sizes[wi] == W_ELEMS / 2)      hint = FMT_PACKED2;
    else if (in_sizes[wi] == W_ELEMS / 8) hint = FMT_PACKED8;

    static bool attr_done = false;
    if (!attr_done) {
        cudaFuncSetAttribute(int4_gemm_kernel,
                             cudaFuncAttributeMaxDynamicSharedMemorySize, SMEM_TOTAL);
        attr_done = true;
    }

    probe_kernel<<<1, 1>>>((const uint32_t*)W, hint);
    convert_transpose_kernel<<<dim3(K_DIM / 64, N_DIM / 64), 256>>>(W);
    a_convert_kernel<<<(M_DIM * K_DIM) / 1024, 256>>>(A);

    dim3 grid(N_DIM / 128, M_DIM / 128);     // (128, 8)
    int4_gemm_kernel<<<grid, 256, SMEM_TOTAL>>>(S, C);
}

// round 7
// speedup vs baseline: 2.6317x; 1.1278x over previous
#include <cuda_runtime.h>
#include <cuda_fp16.h>
#include <cuda_bf16.h>
#include <cstdint>

// IntEinsum: out[b,t,f] = sum_d x[b,t,d] * (W_int4[d,f] / scale[f])
// GEMM M=1024, K=4096, N=16384, fp32 in/out.
// Round 7: ldmatrix.x4 fragment loads (24 LDS -> 6 LDSM per warp/k16),
// 3-stage cp.async pipeline, one barrier per chunk.

#define M_DIM 1024
#define N_DIM 16384
#define K_DIM 4096
#define W_ELEMS (K_DIM * N_DIM)

#define BK 64
#define NCHUNK (K_DIM / BK)          // 64
#define NSTAGE 3

#define RS 72                        // smem row stride (fp16), 144B rows
#define PLANE_BYTES (128 * RS * 2)   // 18432
#define STAGE_BYTES (2 * PLANE_BYTES)// 36864: A | B_t
#define SMEM_TOTAL  (NSTAGE * STAGE_BYTES) // 110592

// ---------------- device scratch ----------------
__device__ __half g_wT[(size_t)N_DIM * K_DIM];   // weights fp16, [n][k]
__device__ __half g_a[M_DIM * K_DIM];            // activations fp16
__device__ int g_fmt;

#define FMT_I8      0
#define FMT_I32     1
#define FMT_F32     2
#define FMT_BF16    3
#define FMT_PACKED2 4
#define FMT_PACKED8 5

__device__ __forceinline__ uint32_t smem_u32(const void* p) {
    uint32_t a;
    asm("{ .reg .u64 t; cvta.to.shared.u64 t, %1; cvt.u32.u64 %0, t; }"
        : "=r"(a) : "l"(p));
    return a;
}

// ---------------- format probe (proven) ----------------
__global__ void probe_kernel(const uint32_t* __restrict__ W, int hint) {
    if (hint >= 0) { g_fmt = hint; return; }
    bool ok = true;
    for (int i = 0; i < 64 && ok; i++) {
        float f = __uint_as_float(W[i]);
        if (!(f >= -8.f && f <= 7.f) || f != rintf(f)) ok = false;
    }
    if (ok) { g_fmt = FMT_F32; return; }
    ok = true;
    for (int i = 0; i < 64 && ok; i++) {
        uint32_t w = W[i];
#pragma unroll
        for (int h = 0; h < 2; h++) {
            uint16_t u = (uint16_t)(w >> (16 * h));
            __nv_bfloat16 b = *reinterpret_cast<__nv_bfloat16*>(&u);
            float f = __bfloat162float(b);
            if (!(f >= -8.f && f <= 7.f) || f != rintf(f)) { ok = false; break; }
        }
    }
    if (ok) { g_fmt = FMT_BF16; return; }
    ok = true;
    for (int i = 0; i < 64 && ok; i++) {
        int v = (int)W[i];
        int hi = v >> 4;
        if (hi != 0 && hi != -1) ok = false;
    }
    g_fmt = ok ? FMT_I32 : FMT_I8;
}

__device__ __forceinline__ int sx_nib(uint32_t w, int shift) {
    return ((int)(w << (28 - shift))) >> 28;
}

__device__ __forceinline__ int decode_w(const void* Wv, int fmt, size_t idx) {
    if (fmt == FMT_F32)  return (int)((const float*)Wv)[idx];
    if (fmt == FMT_BF16) return (int)__bfloat162float(((const __nv_bfloat16*)Wv)[idx]);
    if (fmt == FMT_I32)  return sx_nib(((const uint32_t*)Wv)[idx], 0);
    if (fmt == FMT_I8)   return sx_nib((uint32_t)((const uint8_t*)Wv)[idx], 0);
    if (fmt == FMT_PACKED2) {
        uint32_t b = ((const uint8_t*)Wv)[idx >> 1];
        return sx_nib(b, (int)(idx & 1) * 4);
    }
    uint32_t w = ((const uint32_t*)Wv)[idx >> 3];
    return sx_nib(w, (int)(idx & 7) * 4);
}

// ---------------- W convert + transpose: [k][n] fmt -> [n][k] fp16 ----------------
__global__ void convert_transpose_kernel(const void* __restrict__ Wv) {
    __shared__ __half tile[64 * RS];
    const int fmt = g_fmt;
    const int k0 = blockIdx.x * 64;
    const int n0 = blockIdx.y * 64;
    const int tid = threadIdx.x;

#pragma unroll
    for (int it = 0; it < 16; it++) {
        int idx = tid + it * 256;
        int r = idx >> 6;                      // k-local
        int c = idx & 63;                      // n-local (coalesced reads)
        int e = decode_w(Wv, fmt, (size_t)(k0 + r) * N_DIM + (n0 + c));
        tile[c * RS + r] = __float2half((float)e);
    }
    __syncthreads();
#pragma unroll
    for (int it = 0; it < 2; it++) {
        int q = tid + it * 256;
        int n = q >> 3;
        int cg = q & 7;
        uint4 v = *reinterpret_cast<const uint4*>(&tile[n * RS + cg * 8]);
        *reinterpret_cast<uint4*>(&g_wT[(size_t)(n0 + n) * K_DIM + k0 + cg * 8]) = v;
    }
}

// ---------------- A fp32 -> fp16 ----------------
__global__ void a_convert_kernel(const float* __restrict__ A) {
    size_t i = ((size_t)blockIdx.x * blockDim.x + threadIdx.x) * 4;
    float4 v = *reinterpret_cast<const float4*>(&A[i]);
    __half2 h0 = __floats2half2_rn(v.x, v.y);
    __half2 h1 = __floats2half2_rn(v.z, v.w);
    *reinterpret_cast<uint2*>(&g_a[i]) =
        make_uint2(*(uint32_t*)&h0, *(uint32_t*)&h1);
}

// ---------------- MMA / ldmatrix helpers ----------------
__device__ __forceinline__ void mma_f16(float c[4], uint32_t a0, uint32_t a1,
                                        uint32_t a2, uint32_t a3,
                                        uint32_t b0, uint32_t b1) {
    asm volatile(
        "mma.sync.aligned.m16n8k16.row.col.f32.f16.f16.f32 "
        "{%0,%1,%2,%3}, {%4,%5,%6,%7}, {%8,%9}, {%0,%1,%2,%3};\n"
        : "+f"(c[0]), "+f"(c[1]), "+f"(c[2]), "+f"(c[3])
        : "r"(a0), "r"(a1), "r"(a2), "r"(a3), "r"(b0), "r"(b1));
}

#define LDMATRIX_X4(r0, r1, r2, r3, addr) \
    asm volatile("ldmatrix.sync.aligned.m8n8.x4.shared.b16 {%0,%1,%2,%3}, [%4];" \
        : "=r"(r0), "=r"(r1), "=r"(r2), "=r"(r3) : "r"(addr))

#define CP_ASYNC16(dst, src) \
    asm volatile("cp.async.cg.shared.global [%0], [%1], 16;" \
                 :: "r"(dst), "l"(src) : "memory")
#define CP_COMMIT()  asm volatile("cp.async.commit_group;" ::: "memory")
#define CP_WAIT(n)   asm volatile("cp.async.wait_group %0;" :: "n"(n) : "memory")

// ---------------- GEMM ----------------
__global__ __launch_bounds__(256, 2)
void int4_gemm_kernel(const float* __restrict__ S, float* __restrict__ C) {
    extern __shared__ __align__(128) char smem[];
    const uint32_t smb = smem_u32(smem);

    const int tid    = threadIdx.x;
    const int lane   = tid & 31;
    const int wid    = tid >> 5;
    const int warp_m = wid >> 1;     // 0..3 -> 32 rows
    const int warp_n = wid & 1;      // 0..1 -> 64 cols

    const int bm = blockIdx.y * 128;
    const int bn = blockIdx.x * 128;

    float c[2][8][4];
#pragma unroll
    for (int i = 0; i < 2; i++)
#pragma unroll
        for (int j = 0; j < 8; j++)
#pragma unroll
            for (int q = 0; q < 4; q++) c[i][j][q] = 0.f;

    // ldmatrix lane-address offsets (bytes, within a stage buffer)
    // A (m16k16 per mt): mats = [rows0-7,k0-7][rows8-15,k0-7][rows0-7,k8-15][rows8-15,k8-15]
    const uint32_t aOff =
        (uint32_t)(((warp_m * 32 + ((lane >> 3) & 1) * 8 + (lane & 7)) * RS
                    + ((lane >> 4) & 1) * 8) * 2);
    // B (two n8k16 tiles per x4): mats = [n0-7,k0-7][n0-7,k8-15][n8-15,k0-7][n8-15,k8-15]
    const uint32_t bOff =
        (uint32_t)(((warp_n * 64 + ((lane >> 4) & 1) * 8 + (lane & 7)) * RS
                    + ((lane >> 3) & 1) * 8) * 2);

    auto issue_stage = [&](int chunk) {
        const uint32_t sb = smb + (uint32_t)(chunk % NSTAGE) * STAGE_BYTES;
        const int k0 = chunk * BK;
#pragma unroll
        for (int j = 0; j < 8; j++) {
            const int buf = j >> 2;                 // 0 = A, 1 = B_t
            const int q   = (tid + j * 256) & 1023;
            const int r   = q >> 3;
            const int cg  = q & 7;
            const __half* src = (buf == 0)
                ? &g_a [(size_t)(bm + r) * K_DIM + k0 + cg * 8]
                : &g_wT[(size_t)(bn + r) * K_DIM + k0 + cg * 8];
            CP_ASYNC16(sb + buf * PLANE_BYTES + r * (RS * 2) + cg * 16, src);
        }
    };

    issue_stage(0); CP_COMMIT();
    issue_stage(1); CP_COMMIT();

    for (int i = 0; i < NCHUNK; i++) {
        if (i < NCHUNK - 1) CP_WAIT(1); else CP_WAIT(0);
        __syncthreads();

        if (i + 2 < NCHUNK) { issue_stage(i + 2); CP_COMMIT(); }

        const uint32_t sb    = smb + (uint32_t)(i % NSTAGE) * STAGE_BYTES;
        const uint32_t aBase = sb + aOff;
        const uint32_t bBase = sb + PLANE_BYTES + bOff;

#pragma unroll
        for (int kk = 0; kk < BK; kk += 16) {
            uint32_t a[2][4];
            LDMATRIX_X4(a[0][0], a[0][1], a[0][2], a[0][3], aBase + kk * 2);
            LDMATRIX_X4(a[1][0], a[1][1], a[1][2], a[1][3],
                        aBase + 16 * RS * 2 + kk * 2);

            uint32_t bf[8][2];
#pragma unroll
            for (int p = 0; p < 4; p++) {
                LDMATRIX_X4(bf[2 * p][0], bf[2 * p][1],
                            bf[2 * p + 1][0], bf[2 * p + 1][1],
                            bBase + p * (16 * RS * 2) + kk * 2);
            }

#pragma unroll
            for (int mt = 0; mt < 2; mt++)
#pragma unroll
                for (int nt = 0; nt < 8; nt++)
                    mma_f16(c[mt][nt], a[mt][0], a[mt][1], a[mt][2], a[mt][3],
                            bf[nt][0], bf[nt][1]);
        }
    }

    // ---- epilogue: out = acc / scale[f] ----
    const int row0 = bm + warp_m * 32 + (lane >> 2);
    const int col0 = bn + warp_n * 64 + (lane & 3) * 2;
#pragma unroll
    for (int nt = 0; nt < 8; nt++) {
        int col = col0 + nt * 8;
        float inv0 = 1.0f / S[col];
        float inv1 = 1.0f / S[col + 1];
#pragma unroll
        for (int mt = 0; mt < 2; mt++) {
            int r = row0 + mt * 16;
            float2 v0 = make_float2(c[mt][nt][0] * inv0, c[mt][nt][1] * inv1);
            float2 v1 = make_float2(c[mt][nt][2] * inv0, c[mt][nt][3] * inv1);
            *reinterpret_cast<float2*>(&C[(size_t)r * N_DIM + col])       = v0;
            *reinterpret_cast<float2*>(&C[(size_t)(r + 8) * N_DIM + col]) = v1;
        }
    }
}

// ---------------- launch ----------------
extern "C" void kernel_launch(void* const* d_in, const int* in_sizes, int n_in,
                              void* d_out, int out_size) {
    int ai = 0, si = 2, wi = 1;
    for (int i = 0; i < n_in; i++) {
        if (in_sizes[i] == M_DIM * K_DIM) ai = i;
        else if (in_sizes[i] == N_DIM)    si = i;
        else                              wi = i;
    }
    const float* A = (const float*)d_in[ai];
    const void*  W = d_in[wi];
    const float* S = (const float*)d_in[si];
    float*       C = (float*)d_out;

    int hint = -1;
    if (in_sizes[wi] == W_ELEMS / 2)      hint = FMT_PACKED2;
    else if (in_sizes[wi] == W_ELEMS / 8) hint = FMT_PACKED8;

    static bool attr_done = false;
    if (!attr_done) {
        cudaFuncSetAttribute(int4_gemm_kernel,
                             cudaFuncAttributeMaxDynamicSharedMemorySize, SMEM_TOTAL);
        attr_done = true;
    }

    probe_kernel<<<1, 1>>>((const uint32_t*)W, hint);
    convert_transpose_kernel<<<dim3(K_DIM / 64, N_DIM / 64), 256>>>(W);
    a_convert_kernel<<<(M_DIM * K_DIM) / 1024, 256>>>(A);

    dim3 grid(N_DIM / 128, M_DIM / 128);     // (128, 8)
    int4_gemm_kernel<<<grid, 256, SMEM_TOTAL>>>(S, C);
}

// round 8
// speedup vs baseline: 2.6711x; 1.0150x over previous
#include <cuda_runtime.h>
#include <cuda_fp16.h>
#include <cuda_bf16.h>
#include <cstdint>

// IntEinsum: out[b,t,f] = sum_d x[b,t,d] * (W_int4[d,f] / scale[f])
// GEMM M=1024, K=4096, N=16384, fp32 in/out.
// Round 8: CTA rasterization swap (bm-fastest) so each wave consumes whole
// B columns -> B fetched from DRAM once (128MB), staging hits L2.
// Probe kernel parallelized to one warp. GEMM core frozen from round 7.

#define M_DIM 1024
#define N_DIM 16384
#define K_DIM 4096
#define W_ELEMS (K_DIM * N_DIM)

#define BK 64
#define NCHUNK (K_DIM / BK)          // 64
#define NSTAGE 3

#define RS 72                        // smem row stride (fp16), 144B rows
#define PLANE_BYTES (128 * RS * 2)   // 18432
#define STAGE_BYTES (2 * PLANE_BYTES)// 36864: A | B_t
#define SMEM_TOTAL  (NSTAGE * STAGE_BYTES) // 110592

// ---------------- device scratch ----------------
__device__ __half g_wT[(size_t)N_DIM * K_DIM];   // weights fp16, [n][k]
__device__ __half g_a[M_DIM * K_DIM];            // activations fp16
__device__ int g_fmt;

#define FMT_I8      0
#define FMT_I32     1
#define FMT_F32     2
#define FMT_BF16    3
#define FMT_PACKED2 4
#define FMT_PACKED8 5

__device__ __forceinline__ uint32_t smem_u32(const void* p) {
    uint32_t a;
    asm("{ .reg .u64 t; cvta.to.shared.u64 t, %1; cvt.u32.u64 %0, t; }"
        : "=r"(a) : "l"(p));
    return a;
}

// ---------------- format probe (warp-parallel) ----------------
__global__ void probe_kernel(const uint32_t* __restrict__ W, int hint) {
    if (hint >= 0) { if (threadIdx.x == 0) g_fmt = hint; return; }
    const int lane = threadIdx.x;
    uint32_t w0 = W[lane * 2];
    uint32_t w1 = W[lane * 2 + 1];

    // FP32: word decodes to exact integer in [-8,7]
    bool okf = true;
#pragma unroll
    for (int j = 0; j < 2; j++) {
        float f = __uint_as_float(j ? w1 : w0);
        if (!(f >= -8.f && f <= 7.f) || f != rintf(f)) okf = false;
    }
    if (__all_sync(0xFFFFFFFFu, okf)) { if (lane == 0) g_fmt = FMT_F32; return; }

    // BF16: each half decodes to integer in [-8,7]
    bool okb = true;
#pragma unroll
    for (int j = 0; j < 4; j++) {
        uint16_t u = (uint16_t)((j < 2 ? w0 : w1) >> (16 * (j & 1)));
        __nv_bfloat16 b = *reinterpret_cast<__nv_bfloat16*>(&u);
        float f = __bfloat162float(b);
        if (!(f >= -8.f && f <= 7.f) || f != rintf(f)) okb = false;
    }
    if (__all_sync(0xFFFFFFFFu, okb)) { if (lane == 0) g_fmt = FMT_BF16; return; }

    // I32: upper 28 bits uniform
    bool oki = ((((int)w0) >> 4) == 0 || (((int)w0) >> 4) == -1) &&
               ((((int)w1) >> 4) == 0 || (((int)w1) >> 4) == -1);
    if (lane == 0) g_fmt = __all_sync(0xFFFFFFFFu, oki) ? FMT_I32 : FMT_I8;
}

__device__ __forceinline__ int sx_nib(uint32_t w, int shift) {
    return ((int)(w << (28 - shift))) >> 28;
}

__device__ __forceinline__ int decode_w(const void* Wv, int fmt, size_t idx) {
    if (fmt == FMT_F32)  return (int)((const float*)Wv)[idx];
    if (fmt == FMT_BF16) return (int)__bfloat162float(((const __nv_bfloat16*)Wv)[idx]);
    if (fmt == FMT_I32)  return sx_nib(((const uint32_t*)Wv)[idx], 0);
    if (fmt == FMT_I8)   return sx_nib((uint32_t)((const uint8_t*)Wv)[idx], 0);
    if (fmt == FMT_PACKED2) {
        uint32_t b = ((const uint8_t*)Wv)[idx >> 1];
        return sx_nib(b, (int)(idx & 1) * 4);
    }
    uint32_t w = ((const uint32_t*)Wv)[idx >> 3];
    return sx_nib(w, (int)(idx & 7) * 4);
}

// ---------------- W convert + transpose: [k][n] fmt -> [n][k] fp16 ----------------
__global__ void convert_transpose_kernel(const void* __restrict__ Wv) {
    __shared__ __half tile[64 * RS];
    const int fmt = g_fmt;
    const int k0 = blockIdx.x * 64;
    const int n0 = blockIdx.y * 64;
    const int tid = threadIdx.x;

#pragma unroll
    for (int it = 0; it < 16; it++) {
        int idx = tid + it * 256;
        int r = idx >> 6;                      // k-local
        int c = idx & 63;                      // n-local (coalesced reads)
        int e = decode_w(Wv, fmt, (size_t)(k0 + r) * N_DIM + (n0 + c));
        tile[c * RS + r] = __float2half((float)e);
    }
    __syncthreads();
#pragma unroll
    for (int it = 0; it < 2; it++) {
        int q = tid + it * 256;
        int n = q >> 3;
        int cg = q & 7;
        uint4 v = *reinterpret_cast<const uint4*>(&tile[n * RS + cg * 8]);
        *reinterpret_cast<uint4*>(&g_wT[(size_t)(n0 + n) * K_DIM + k0 + cg * 8]) = v;
    }
}

// ---------------- A fp32 -> fp16 ----------------
__global__ void a_convert_kernel(const float* __restrict__ A) {
    size_t i = ((size_t)blockIdx.x * blockDim.x + threadIdx.x) * 4;
    float4 v = *reinterpret_cast<const float4*>(&A[i]);
    __half2 h0 = __floats2half2_rn(v.x, v.y);
    __half2 h1 = __floats2half2_rn(v.z, v.w);
    *reinterpret_cast<uint2*>(&g_a[i]) =
        make_uint2(*(uint32_t*)&h0, *(uint32_t*)&h1);
}

// ---------------- MMA / ldmatrix helpers ----------------
__device__ __forceinline__ void mma_f16(float c[4], uint32_t a0, uint32_t a1,
                                        uint32_t a2, uint32_t a3,
                                        uint32_t b0, uint32_t b1) {
    asm volatile(
        "mma.sync.aligned.m16n8k16.row.col.f32.f16.f16.f32 "
        "{%0,%1,%2,%3}, {%4,%5,%6,%7}, {%8,%9}, {%0,%1,%2,%3};\n"
        : "+f"(c[0]), "+f"(c[1]), "+f"(c[2]), "+f"(c[3])
        : "r"(a0), "r"(a1), "r"(a2), "r"(a3), "r"(b0), "r"(b1));
}

#define LDMATRIX_X4(r0, r1, r2, r3, addr) \
    asm volatile("ldmatrix.sync.aligned.m8n8.x4.shared.b16 {%0,%1,%2,%3}, [%4];" \
        : "=r"(r0), "=r"(r1), "=r"(r2), "=r"(r3) : "r"(addr))

#define CP_ASYNC16(dst, src) \
    asm volatile("cp.async.cg.shared.global [%0], [%1], 16;" \
                 :: "r"(dst), "l"(src) : "memory")
#define CP_COMMIT()  asm volatile("cp.async.commit_group;" ::: "memory")
#define CP_WAIT(n)   asm volatile("cp.async.wait_group %0;" :: "n"(n) : "memory")

// ---------------- GEMM ----------------
__global__ __launch_bounds__(256, 2)
void int4_gemm_kernel(const float* __restrict__ S, float* __restrict__ C) {
    extern __shared__ __align__(128) char smem[];
    const uint32_t smb = smem_u32(smem);

    const int tid    = threadIdx.x;
    const int lane   = tid & 31;
    const int wid    = tid >> 5;
    const int warp_m = wid >> 1;     // 0..3 -> 32 rows
    const int warp_n = wid & 1;      // 0..1 -> 64 cols

    // bm-fastest rasterization: one wave = all 8 bm x ~37 bn columns,
    // so each bn's B slice is consumed entirely within a wave (B DRAM once).
    const int bm = blockIdx.x * 128;
    const int bn = blockIdx.y * 128;

    float c[2][8][4];
#pragma unroll
    for (int i = 0; i < 2; i++)
#pragma unroll
        for (int j = 0; j < 8; j++)
#pragma unroll
            for (int q = 0; q < 4; q++) c[i][j][q] = 0.f;

    // ldmatrix lane-address offsets (bytes, within a stage buffer)
    const uint32_t aOff =
        (uint32_t)(((warp_m * 32 + ((lane >> 3) & 1) * 8 + (lane & 7)) * RS
                    + ((lane >> 4) & 1) * 8) * 2);
    const uint32_t bOff =
        (uint32_t)(((warp_n * 64 + ((lane >> 4) & 1) * 8 + (lane & 7)) * RS
                    + ((lane >> 3) & 1) * 8) * 2);

    auto issue_stage = [&](int chunk) {
        const uint32_t sb = smb + (uint32_t)(chunk % NSTAGE) * STAGE_BYTES;
        const int k0 = chunk * BK;
#pragma unroll
        for (int j = 0; j < 8; j++) {
            const int buf = j >> 2;                 // 0 = A, 1 = B_t
            const int q   = (tid + j * 256) & 1023;
            const int r   = q >> 3;
            const int cg  = q & 7;
            const __half* src = (buf == 0)
                ? &g_a [(size_t)(bm + r) * K_DIM + k0 + cg * 8]
                : &g_wT[(size_t)(bn + r) * K_DIM + k0 + cg * 8];
            CP_ASYNC16(sb + buf * PLANE_BYTES + r * (RS * 2) + cg * 16, src);
        }
    };

    issue_stage(0); CP_COMMIT();
    issue_stage(1); CP_COMMIT();

    for (int i = 0; i < NCHUNK; i++) {
        if (i < NCHUNK - 1) CP_WAIT(1); else CP_WAIT(0);
        __syncthreads();

        if (i + 2 < NCHUNK) { issue_stage(i + 2); CP_COMMIT(); }

        const uint32_t sb    = smb + (uint32_t)(i % NSTAGE) * STAGE_BYTES;
        const uint32_t aBase = sb + aOff;
        const uint32_t bBase = sb + PLANE_BYTES + bOff;

#pragma unroll
        for (int kk = 0; kk < BK; kk += 16) {
            uint32_t a[2][4];
            LDMATRIX_X4(a[0][0], a[0][1], a[0][2], a[0][3], aBase + kk * 2);
            LDMATRIX_X4(a[1][0], a[1][1], a[1][2], a[1][3],
                        aBase + 16 * RS * 2 + kk * 2);

            uint32_t bf[8][2];
#pragma unroll
            for (int p = 0; p < 4; p++) {
                LDMATRIX_X4(bf[2 * p][0], bf[2 * p][1],
                            bf[2 * p + 1][0], bf[2 * p + 1][1],
                            bBase + p * (16 * RS * 2) + kk * 2);
            }

#pragma unroll
            for (int mt = 0; mt < 2; mt++)
#pragma unroll
                for (int nt = 0; nt < 8; nt++)
                    mma_f16(c[mt][nt], a[mt][0], a[mt][1], a[mt][2], a[mt][3],
                            bf[nt][0], bf[nt][1]);
        }
    }

    // ---- epilogue: out = acc / scale[f] ----
    const int row0 = bm + warp_m * 32 + (lane >> 2);
    const int col0 = bn + warp_n * 64 + (lane & 3) * 2;
#pragma unroll
    for (int nt = 0; nt < 8; nt++) {
        int col = col0 + nt * 8;
        float inv0 = 1.0f / S[col];
        float inv1 = 1.0f / S[col + 1];
#pragma unroll
        for (int mt = 0; mt < 2; mt++) {
            int r = row0 + mt * 16;
            float2 v0 = make_float2(c[mt][nt][0] * inv0, c[mt][nt][1] * inv1);
            float2 v1 = make_float2(c[mt][nt][2] * inv0, c[mt][nt][3] * inv1);
            *reinterpret_cast<float2*>(&C[(size_t)r * N_DIM + col])       = v0;
            *reinterpret_cast<float2*>(&C[(size_t)(r + 8) * N_DIM + col]) = v1;
        }
    }
}

// ---------------- launch ----------------
extern "C" void kernel_launch(void* const* d_in, const int* in_sizes, int n_in,
                              void* d_out, int out_size) {
    int ai = 0, si = 2, wi = 1;
    for (int i = 0; i < n_in; i++) {
        if (in_sizes[i] == M_DIM * K_DIM) ai = i;
        else if (in_sizes[i] == N_DIM)    si = i;
        else                              wi = i;
    }
    const float* A = (const float*)d_in[ai];
    const void*  W = d_in[wi];
    const float* S = (const float*)d_in[si];
    float*       C = (float*)d_out;

    int hint = -1;
    if (in_sizes[wi] == W_ELEMS / 2)      hint = FMT_PACKED2;
    else if (in_sizes[wi] == W_ELEMS / 8) hint = FMT_PACKED8;

    static bool attr_done = false;
    if (!attr_done) {
        cudaFuncSetAttribute(int4_gemm_kernel,
                             cudaFuncAttributeMaxDynamicSharedMemorySize, SMEM_TOTAL);
        attr_done = true;
    }

    probe_kernel<<<1, 32>>>((const uint32_t*)W, hint);
    convert_transpose_kernel<<<dim3(K_DIM / 64, N_DIM / 64), 256>>>(W);
    a_convert_kernel<<<(M_DIM * K_DIM) / 1024, 256>>>(A);

    dim3 grid(M_DIM / 128, N_DIM / 128);     // (8, 128) -- bm fastest
    int4_gemm_kernel<<<grid, 256, SMEM_TOTAL>>>(S, C);
}

// round 9
// speedup vs baseline: 2.7725x; 1.0380x over previous
#include <cuda_runtime.h>
#include <cuda_fp16.h>
#include <cuda_bf16.h>
#include <cstdint>

// IntEinsum: out[b,t,f] = sum_d x[b,t,d] * (W_int4[d,f] / scale[f])
// GEMM M=1024, K=4096, N=16384, fp32 in/out.
// Round 9: remove per-chunk __syncthreads lockstep. mbarrier full/empty
// handshake per pipeline stage (cp.async.mbarrier.arrive.noinc producers,
// per-warp empty arrivals) lets warps drift and cover each other's
// LDSM->MMA dependency windows. GEMM core math frozen from round 7/8.

#define M_DIM 1024
#define N_DIM 16384
#define K_DIM 4096
#define W_ELEMS (K_DIM * N_DIM)

#define BK 64
#define NCHUNK (K_DIM / BK)          // 64
#define NSTAGE 3

#define RS 72                        // smem row stride (fp16), 144B rows
#define PLANE_BYTES (128 * RS * 2)   // 18432
#define STAGE_BYTES (2 * PLANE_BYTES)// 36864: A | B_t
#define BAR_OFF     (NSTAGE * STAGE_BYTES)      // 110592
#define SMEM_TOTAL  (BAR_OFF + 64)              // barriers: full/empty x3

// ---------------- device scratch ----------------
__device__ __half g_wT[(size_t)N_DIM * K_DIM];   // weights fp16, [n][k]
__device__ __half g_a[M_DIM * K_DIM];            // activations fp16
__device__ int g_fmt;

#define FMT_I8      0
#define FMT_I32     1
#define FMT_F32     2
#define FMT_BF16    3
#define FMT_PACKED2 4
#define FMT_PACKED8 5

__device__ __forceinline__ uint32_t smem_u32(const void* p) {
    uint32_t a;
    asm("{ .reg .u64 t; cvta.to.shared.u64 t, %1; cvt.u32.u64 %0, t; }"
        : "=r"(a) : "l"(p));
    return a;
}

// ---------------- format probe (warp-parallel, proven) ----------------
__global__ void probe_kernel(const uint32_t* __restrict__ W, int hint) {
    if (hint >= 0) { if (threadIdx.x == 0) g_fmt = hint; return; }
    const int lane = threadIdx.x;
    uint32_t w0 = W[lane * 2];
    uint32_t w1 = W[lane * 2 + 1];

    bool okf = true;
#pragma unroll
    for (int j = 0; j < 2; j++) {
        float f = __uint_as_float(j ? w1 : w0);
        if (!(f >= -8.f && f <= 7.f) || f != rintf(f)) okf = false;
    }
    if (__all_sync(0xFFFFFFFFu, okf)) { if (lane == 0) g_fmt = FMT_F32; return; }

    bool okb = true;
#pragma unroll
    for (int j = 0; j < 4; j++) {
        uint16_t u = (uint16_t)((j < 2 ? w0 : w1) >> (16 * (j & 1)));
        __nv_bfloat16 b = *reinterpret_cast<__nv_bfloat16*>(&u);
        float f = __bfloat162float(b);
        if (!(f >= -8.f && f <= 7.f) || f != rintf(f)) okb = false;
    }
    if (__all_sync(0xFFFFFFFFu, okb)) { if (lane == 0) g_fmt = FMT_BF16; return; }

    bool oki = ((((int)w0) >> 4) == 0 || (((int)w0) >> 4) == -1) &&
               ((((int)w1) >> 4) == 0 || (((int)w1) >> 4) == -1);
    if (lane == 0) g_fmt = __all_sync(0xFFFFFFFFu, oki) ? FMT_I32 : FMT_I8;
}

__device__ __forceinline__ int sx_nib(uint32_t w, int shift) {
    return ((int)(w << (28 - shift))) >> 28;
}

__device__ __forceinline__ int decode_w(const void* Wv, int fmt, size_t idx) {
    if (fmt == FMT_F32)  return (int)((const float*)Wv)[idx];
    if (fmt == FMT_BF16) return (int)__bfloat162float(((const __nv_bfloat16*)Wv)[idx]);
    if (fmt == FMT_I32)  return sx_nib(((const uint32_t*)Wv)[idx], 0);
    if (fmt == FMT_I8)   return sx_nib((uint32_t)((const uint8_t*)Wv)[idx], 0);
    if (fmt == FMT_PACKED2) {
        uint32_t b = ((const uint8_t*)Wv)[idx >> 1];
        return sx_nib(b, (int)(idx & 1) * 4);
    }
    uint32_t w = ((const uint32_t*)Wv)[idx >> 3];
    return sx_nib(w, (int)(idx & 7) * 4);
}

// ---------------- W convert + transpose: [k][n] fmt -> [n][k] fp16 ----------------
__global__ void convert_transpose_kernel(const void* __restrict__ Wv) {
    __shared__ __half tile[64 * RS];
    const int fmt = g_fmt;
    const int k0 = blockIdx.x * 64;
    const int n0 = blockIdx.y * 64;
    const int tid = threadIdx.x;

#pragma unroll
    for (int it = 0; it < 16; it++) {
        int idx = tid + it * 256;
        int r = idx >> 6;                      // k-local
        int c = idx & 63;                      // n-local (coalesced reads)
        int e = decode_w(Wv, fmt, (size_t)(k0 + r) * N_DIM + (n0 + c));
        tile[c * RS + r] = __float2half((float)e);
    }
    __syncthreads();
#pragma unroll
    for (int it = 0; it < 2; it++) {
        int q = tid + it * 256;
        int n = q >> 3;
        int cg = q & 7;
        uint4 v = *reinterpret_cast<const uint4*>(&tile[n * RS + cg * 8]);
        *reinterpret_cast<uint4*>(&g_wT[(size_t)(n0 + n) * K_DIM + k0 + cg * 8]) = v;
    }
}

// ---------------- A fp32 -> fp16 ----------------
__global__ void a_convert_kernel(const float* __restrict__ A) {
    size_t i = ((size_t)blockIdx.x * blockDim.x + threadIdx.x) * 4;
    float4 v = *reinterpret_cast<const float4*>(&A[i]);
    __half2 h0 = __floats2half2_rn(v.x, v.y);
    __half2 h1 = __floats2half2_rn(v.z, v.w);
    *reinterpret_cast<uint2*>(&g_a[i]) =
        make_uint2(*(uint32_t*)&h0, *(uint32_t*)&h1);
}

// ---------------- MMA / ldmatrix / mbarrier helpers ----------------
__device__ __forceinline__ void mma_f16(float c[4], uint32_t a0, uint32_t a1,
                                        uint32_t a2, uint32_t a3,
                                        uint32_t b0, uint32_t b1) {
    asm volatile(
        "mma.sync.aligned.m16n8k16.row.col.f32.f16.f16.f32 "
        "{%0,%1,%2,%3}, {%4,%5,%6,%7}, {%8,%9}, {%0,%1,%2,%3};\n"
        : "+f"(c[0]), "+f"(c[1]), "+f"(c[2]), "+f"(c[3])
        : "r"(a0), "r"(a1), "r"(a2), "r"(a3), "r"(b0), "r"(b1));
}

#define LDMATRIX_X4(r0, r1, r2, r3, addr) \
    asm volatile("ldmatrix.sync.aligned.m8n8.x4.shared.b16 {%0,%1,%2,%3}, [%4];" \
        : "=r"(r0), "=r"(r1), "=r"(r2), "=r"(r3) : "r"(addr))

#define CP_ASYNC16(dst, src) \
    asm volatile("cp.async.cg.shared.global [%0], [%1], 16;" \
                 :: "r"(dst), "l"(src) : "memory")
#define CP_MBAR_ARRIVE(addr) \
    asm volatile("cp.async.mbarrier.arrive.noinc.shared.b64 [%0];" \
                 :: "r"(addr) : "memory")

#define MBARRIER_INIT(addr, cnt) \
    asm volatile("mbarrier.init.shared.b64 [%0], %1;" :: "r"(addr), "r"(cnt) : "memory")
#define MBARRIER_ARRIVE(addr) \
    asm volatile("mbarrier.arrive.shared.b64 _, [%0];" :: "r"(addr) : "memory")
#define MBARRIER_WAIT_PARITY(addr, ph) do {                                         \
    uint32_t _m = (addr); uint32_t _p = (ph); uint32_t _d;                          \
    asm volatile("{\n\t.reg .pred p;\n\t"                                           \
        "mbarrier.try_wait.parity.acquire.cta.shared::cta.b64 p, [%1], %2;\n\t"     \
        "selp.b32 %0, 1, 0, p;\n\t}" : "=r"(_d) : "r"(_m), "r"(_p) : "memory");     \
    if (!_d) {                                                                      \
        asm volatile("{\n\t.reg .pred P1;\n\t"                                      \
            "W%=:\n\t"                                                              \
            "mbarrier.try_wait.parity.acquire.cta.shared::cta.b64 P1, [%0], %1, 0x989680;\n\t" \
            "@P1 bra.uni D%=;\n\t"                                                  \
            "bra.uni W%=;\n\t"                                                      \
            "D%=:\n\t}" :: "r"(_m), "r"(_p) : "memory");                            \
    }                                                                               \
} while (0)

// ---------------- GEMM ----------------
__global__ __launch_bounds__(256, 2)
void int4_gemm_kernel(const float* __restrict__ S, float* __restrict__ C) {
    extern __shared__ __align__(128) char smem[];
    const uint32_t smb = smem_u32(smem);

    const int tid    = threadIdx.x;
    const int lane   = tid & 31;
    const int wid    = tid >> 5;
    const int warp_m = wid >> 1;     // 0..3 -> 32 rows
    const int warp_n = wid & 1;      // 0..1 -> 64 cols

    // bm-fastest rasterization (keeps B DRAM-once behavior from round 8)
    const int bm = blockIdx.x * 128;
    const int bn = blockIdx.y * 128;

    // barriers: full[s] = smb+BAR_OFF+s*16, empty[s] = +8
    const uint32_t barb = smb + BAR_OFF;
    if (tid == 0) {
#pragma unroll
        for (int s = 0; s < NSTAGE; s++) {
            MBARRIER_INIT(barb + s * 16,     256);  // full: one cp-arrive/thread
            MBARRIER_INIT(barb + s * 16 + 8, 8);    // empty: one arrive/warp
        }
    }
    __syncthreads();

    float c[2][8][4];
#pragma unroll
    for (int i = 0; i < 2; i++)
#pragma unroll
        for (int j = 0; j < 8; j++)
#pragma unroll
            for (int q = 0; q < 4; q++) c[i][j][q] = 0.f;

    const uint32_t aOff =
        (uint32_t)(((warp_m * 32 + ((lane >> 3) & 1) * 8 + (lane & 7)) * RS
                    + ((lane >> 4) & 1) * 8) * 2);
    const uint32_t bOff =
        (uint32_t)(((warp_n * 64 + ((lane >> 4) & 1) * 8 + (lane & 7)) * RS
                    + ((lane >> 3) & 1) * 8) * 2);

    auto issue_stage = [&](int chunk) {
        const uint32_t sb = smb + (uint32_t)(chunk % NSTAGE) * STAGE_BYTES;
        const int k0 = chunk * BK;
#pragma unroll
        for (int j = 0; j < 8; j++) {
            const int buf = j >> 2;                 // 0 = A, 1 = B_t
            const int q   = (tid + j * 256) & 1023;
            const int r   = q >> 3;
            const int cg  = q & 7;
            const __half* src = (buf == 0)
                ? &g_a [(size_t)(bm + r) * K_DIM + k0 + cg * 8]
                : &g_wT[(size_t)(bn + r) * K_DIM + k0 + cg * 8];
            CP_ASYNC16(sb + buf * PLANE_BYTES + r * (RS * 2) + cg * 16, src);
        }
    };

    // prologue: stage chunks 0..2 into virgin buffers (no empty wait)
#pragma unroll
    for (int p = 0; p < NSTAGE; p++) {
        issue_stage(p);
        CP_MBAR_ARRIVE(barb + p * 16);
    }

    int s = 0, fp = 0;
    for (int i = 0; i < NCHUNK; i++) {
        const uint32_t fullb  = barb + s * 16;
        const uint32_t emptyb = fullb + 8;

        MBARRIER_WAIT_PARITY(fullb, fp);

        const uint32_t sb    = smb + (uint32_t)s * STAGE_BYTES;
        const uint32_t aBase = sb + aOff;
        const uint32_t bBase = sb + PLANE_BYTES + bOff;

#pragma unroll
        for (int kk = 0; kk < BK; kk += 16) {
            uint32_t a[2][4];
            LDMATRIX_X4(a[0][0], a[0][1], a[0][2], a[0][3], aBase + kk * 2);
            LDMATRIX_X4(a[1][0], a[1][1], a[1][2], a[1][3],
                        aBase + 16 * RS * 2 + kk * 2);

            uint32_t bf[8][2];
#pragma unroll
            for (int p = 0; p < 4; p++) {
                LDMATRIX_X4(bf[2 * p][0], bf[2 * p][1],
                            bf[2 * p + 1][0], bf[2 * p + 1][1],
                            bBase + p * (16 * RS * 2) + kk * 2);
            }

#pragma unroll
            for (int mt = 0; mt < 2; mt++)
#pragma unroll
                for (int nt = 0; nt < 8; nt++)
                    mma_f16(c[mt][nt], a[mt][0], a[mt][1], a[mt][2], a[mt][3],
                            bf[nt][0], bf[nt][1]);
        }

        // whole warp done reading stage s for this chunk (ldmatrix is
        // warp-collective) -> one arrive per warp
        if (lane == 0) MBARRIER_ARRIVE(emptyb);

        // stage chunk i+NSTAGE into this buffer once all warps released it
        if (i + NSTAGE < NCHUNK) {
            MBARRIER_WAIT_PARITY(emptyb, fp);
            issue_stage(i + NSTAGE);
            CP_MBAR_ARRIVE(fullb);
        }

        if (++s == NSTAGE) { s = 0; fp ^= 1; }
    }

    // ---- epilogue: out = acc / scale[f] ----
    const int row0 = bm + warp_m * 32 + (lane >> 2);
    const int col0 = bn + warp_n * 64 + (lane & 3) * 2;
#pragma unroll
    for (int nt = 0; nt < 8; nt++) {
        int col = col0 + nt * 8;
        float inv0 = 1.0f / S[col];
        float inv1 = 1.0f / S[col + 1];
#pragma unroll
        for (int mt = 0; mt < 2; mt++) {
            int r = row0 + mt * 16;
            float2 v0 = make_float2(c[mt][nt][0] * inv0, c[mt][nt][1] * inv1);
            float2 v1 = make_float2(c[mt][nt][2] * inv0, c[mt][nt][3] * inv1);
            *reinterpret_cast<float2*>(&C[(size_t)r * N_DIM + col])       = v0;
            *reinterpret_cast<float2*>(&C[(size_t)(r + 8) * N_DIM + col]) = v1;
        }
    }
}

// ---------------- launch ----------------
extern "C" void kernel_launch(void* const* d_in, const int* in_sizes, int n_in,
                              void* d_out, int out_size) {
    int ai = 0, si = 2, wi = 1;
    for (int i = 0; i < n_in; i++) {
        if (in_sizes[i] == M_DIM * K_DIM) ai = i;
        else if (in_sizes[i] == N_DIM)    si = i;
        else                              wi = i;
    }
    const float* A = (const float*)d_in[ai];
    const void*  W = d_in[wi];
    const float* S = (const float*)d_in[si];
    float*       C = (float*)d_out;

    int hint = -1;
    if (in_sizes[wi] == W_ELEMS / 2)      hint = FMT_PACKED2;
    else if (in_sizes[wi] == W_ELEMS / 8) hint = FMT_PACKED8;

    static bool attr_done = false;
    if (!attr_done) {
        cudaFuncSetAttribute(int4_gemm_kernel,
                             cudaFuncAttributeMaxDynamicSharedMemorySize, SMEM_TOTAL);
        attr_done = true;
    }

    probe_kernel<<<1, 32>>>((const uint32_t*)W, hint);
    convert_transpose_kernel<<<dim3(K_DIM / 64, N_DIM / 64), 256>>>(W);
    a_convert_kernel<<<(M_DIM * K_DIM) / 1024, 256>>>(A);

    dim3 grid(M_DIM / 128, N_DIM / 128);     // (8, 128) -- bm fastest
    int4_gemm_kernel<<<grid, 256, SMEM_TOTAL>>>(S, C);
}